// round 15
// baseline (speedup 1.0000x reference)
#include <cuda_runtime.h>
#include <cstdint>
#include <math_constants.h>

// Problem constants
#define BATCH      64
#define SEQ        2048
#define H_DIM      1024
#define NSPLIT     8
#define ROWS_PER_CTA (SEQ / NSPLIT)            // 256
#define STAGE_ROWS 8
#define NSTAGES    (ROWS_PER_CTA / STAGE_ROWS) // 32
#define NBUF       3
#define STAGE_BYTES (STAGE_ROWS * H_DIM * 4)   // 32768
#define SMEM_BUF_BYTES (NBUF * STAGE_BYTES)    // 98304
#define SMEM_TOTAL (SMEM_BUF_BYTES + 128)      // 98432 -> 2 CTAs/SM
#define WORK_CTAS  (BATCH * NSPLIT)            // 512
#define GRID       (WORK_CTAS + BATCH)         // 512 work + 64 combine

typedef unsigned long long u64;

// Cross-CTA scratch (allocation-free: __device__ globals, zero-initialized)
__device__ float g_num[BATCH * NSPLIT * H_DIM];   // per-split exp-weighted numerator
__device__ float g_ml[BATCH * NSPLIT * 2];        // per-split (M, L)
__device__ int   g_cnt[BATCH];                    // arrival counters (combine CTA resets)

// ---------------- PTX helpers ----------------
__device__ __forceinline__ uint32_t smem_u32(const void* p) {
    uint32_t a;
    asm("{ .reg .u64 t; cvta.to.shared.u64 t, %1; cvt.u32.u64 %0, t; }"
        : "=r"(a) : "l"(p));
    return a;
}

// Packed f32x2 ops (Blackwell FFMA2 — only reachable via PTX)
__device__ __forceinline__ u64 fma2(u64 a, u64 b, u64 c) {
    u64 d; asm("fma.rn.f32x2 %0, %1, %2, %3;" : "=l"(d) : "l"(a), "l"(b), "l"(c));
    return d;
}
__device__ __forceinline__ u64 add2(u64 a, u64 b) {
    u64 d; asm("add.rn.f32x2 %0, %1, %2;" : "=l"(d) : "l"(a), "l"(b));
    return d;
}
__device__ __forceinline__ u64 pack2(float lo, float hi) {
    u64 r; asm("mov.b64 %0, {%1, %2};" : "=l"(r) : "f"(lo), "f"(hi));
    return r;
}
__device__ __forceinline__ void unpack2(u64 v, float& lo, float& hi) {
    asm("mov.b64 {%0, %1}, %2;" : "=f"(lo), "=f"(hi) : "l"(v));
}

#define MBARRIER_INIT(addr, count) \
    asm volatile("mbarrier.init.shared.b64 [%0], %1;" \
                 :: "r"((uint32_t)(addr)), "r"((uint32_t)(count)) : "memory")

#define MBARRIER_EXPECT_TX(addr, bytes) \
    asm volatile("mbarrier.arrive.expect_tx.shared.b64 _, [%0], %1;" \
                 :: "r"((uint32_t)(addr)), "r"((uint32_t)(bytes)) : "memory")

#define MBARRIER_WAIT_PARITY(mbar_smem_addr, phase_parity) do { \
    uint32_t _mbar = (uint32_t)(mbar_smem_addr); \
    uint32_t _parity = (uint32_t)(phase_parity); \
    uint32_t _done; \
    asm volatile( \
        "{\n\t" \
        ".reg .pred p;\n\t" \
        "mbarrier.try_wait.parity.acquire.cta.shared::cta.b64 p, [%1], %2;\n\t" \
        "selp.b32 %0, 1, 0, p;\n\t" \
        "}" \
        : "=r"(_done) : "r"(_mbar), "r"(_parity) : "memory"); \
    if (!_done) { \
        asm volatile( \
            "{\n\t" \
            ".reg .pred P1;\n\t" \
            "WAIT_LOOP_%=:\n\t" \
            "mbarrier.try_wait.parity.acquire.cta.shared::cta.b64 P1, [%0], %1, 0x989680;\n\t" \
            "@P1 bra.uni WAIT_DONE_%=;\n\t" \
            "bra.uni WAIT_LOOP_%=;\n\t" \
            "WAIT_DONE_%=:\n\t" \
            "}" \
            :: "r"(_mbar), "r"(_parity) : "memory"); \
    } \
} while (0)

#define BULK_G2S(dst_smem, src_gmem, nbytes, mbar) \
    asm volatile("cp.async.bulk.shared::cluster.global.mbarrier::complete_tx::bytes " \
                 "[%0], [%1], %2, [%3];" \
                 :: "r"((uint32_t)(dst_smem)), "l"(src_gmem), \
                    "r"((uint32_t)(nbytes)), "r"((uint32_t)(mbar)) : "memory")

// ---------------- One kernel, two roles, 2 CTAs/SM (FINAL) ----------------
// blockIdx < 512: work CTA — stream 256 seq rows (1 MiB) through a 3-deep
//   pipeline of 32 KiB (8-row) stages. Warp w consumes row w of each stage.
//   Co-resident CTA on the same SM fills DRAM-demand gaps (barriers, epilogue).
// blockIdx >= 512: combine CTA for batch b — waits for 8 splits, merges
//   from L2, writes output. Overlapped with the work waves.
// Measured: 6572 GB/s — at the sm_103a LTS throughput ceiling (~6300 B/cyc,
// path-independent); kernel time within ~1 us of the 512 MiB streaming floor.
__global__ void __launch_bounds__(256, 2)
attn_kernel(const float* __restrict__ enc, const float* __restrict__ hn,
            float* __restrict__ out)
{
    const int tid = threadIdx.x;

    // ================= Combine role =================
    if (blockIdx.x >= WORK_CTAS) {
        const int b = blockIdx.x - WORK_CTAS;
        __shared__ int ready;
        if (tid == 0) {
            while (atomicAdd(&g_cnt[b], 0) != NSPLIT) __nanosleep(200);
            g_cnt[b] = 0;                 // self-reset for next graph replay
            ready = 1;
        }
        __syncthreads();
        (void)ready;
        __threadfence();                  // acquire partials

        float ml_m[NSPLIT], ml_l[NSPLIT];
#pragma unroll
        for (int s2 = 0; s2 < NSPLIT; s2++) {
            ml_m[s2] = g_ml[(b * NSPLIT + s2) * 2 + 0];
            ml_l[s2] = g_ml[(b * NSPLIT + s2) * 2 + 1];
        }
        float GM = ml_m[0];
#pragma unroll
        for (int s2 = 1; s2 < NSPLIT; s2++) GM = fmaxf(GM, ml_m[s2]);
        float GL = 0.f;
#pragma unroll
        for (int s2 = 0; s2 < NSPLIT; s2++) GL += ml_l[s2] * __expf(ml_m[s2] - GM);

        float4 a = make_float4(0.f, 0.f, 0.f, 0.f);
        const float4* num4 = (const float4*)g_num;
#pragma unroll
        for (int s2 = 0; s2 < NSPLIT; s2++) {
            const float fs = __expf(ml_m[s2] - GM);
            const float4 t = num4[(size_t)(b * NSPLIT + s2) * 256 + tid];
            a.x += fs * t.x; a.y += fs * t.y; a.z += fs * t.z; a.w += fs * t.w;
        }
        const float inv = 1.0f / GL;

        float4* out4 = (float4*)out;
        out4[(size_t)b * 512 + tid] = ((const float4*)(hn + (size_t)b * H_DIM))[tid];
        float4 ctx;
        ctx.x = a.x * inv; ctx.y = a.y * inv; ctx.z = a.z * inv; ctx.w = a.w * inv;
        out4[(size_t)b * 512 + 256 + tid] = ctx;
        return;
    }

    // ================= Work role =================
    extern __shared__ char smem[];
    const int wid = tid >> 5;
    const int ln  = tid & 31;
    const int b   = blockIdx.x / NSPLIT;
    const int sp  = blockIdx.x % NSPLIT;

    const char* src_base =
        (const char*)(enc + ((size_t)b * SEQ + (size_t)sp * ROWS_PER_CTA) * H_DIM);

    const uint32_t sbase = smem_u32(smem);
    const uint32_t mbar0 = sbase + SMEM_BUF_BYTES;
    float* msh = (float*)(smem + SMEM_BUF_BYTES + 32);
    float* lsh = msh + 8;

    if (tid == 0) {
#pragma unroll
        for (int s = 0; s < NBUF; s++) MBARRIER_INIT(mbar0 + 8 * s, 1);
    }
    __syncthreads();

    // h_n[b] as packed f32x2 pairs matching the per-lane column map
    const ulonglong2* h2 = (const ulonglong2*)(hn + (size_t)b * H_DIM);
    ulonglong2 hreg[8];
#pragma unroll
    for (int i = 0; i < 8; i++) hreg[i] = h2[i * 32 + ln];

    float m = -CUDART_INF_F;
    float l = 0.f;
    u64 acc[16];
#pragma unroll
    for (int i = 0; i < 16; i++) acc[i] = 0ull;

    // Prologue: fill the pipeline
    if (tid == 0) {
#pragma unroll
        for (int s = 0; s < NBUF; s++) {
            MBARRIER_EXPECT_TX(mbar0 + 8 * s, STAGE_BYTES);
            BULK_G2S(sbase + s * STAGE_BYTES,
                     src_base + (size_t)s * STAGE_BYTES,
                     STAGE_BYTES, mbar0 + 8 * s);
        }
    }

    for (int st = 0; st < NSTAGES; st++) {
        const int bsel = st % NBUF;
        const int par  = (st / NBUF) & 1;
        MBARRIER_WAIT_PARITY(mbar0 + 8 * bsel, par);

        // Warp wid consumes row wid of this 8-row stage
        {
            const ulonglong2* row = (const ulonglong2*)
                (smem + (size_t)bsel * STAGE_BYTES + (size_t)wid * (H_DIM * 4));
            ulonglong2 v[8];
#pragma unroll
            for (int i = 0; i < 8; i++) v[i] = row[i * 32 + ln];   // 16B lane stride: conflict-free

            // Packed dot: 16 fma2, 2 independent chains
            u64 p0 = 0ull, p1 = 0ull;
#pragma unroll
            for (int i = 0; i < 8; i++) {
                p0 = fma2(v[i].x, hreg[i].x, p0);
                p1 = fma2(v[i].y, hreg[i].y, p1);
            }
            float dl, dh;
            unpack2(add2(p0, p1), dl, dh);
            float d = dl + dh;
#pragma unroll
            for (int off = 16; off; off >>= 1)
                d += __shfl_xor_sync(0xffffffffu, d, off);

            // Warp-uniform branch: d identical across lanes
            if (d > m) {
                const float cf = __expf(m - d);    // exp(-inf)=0 on first row
                m = d;
                l = l * cf + 1.f;
                const u64 cf2 = pack2(cf, cf);
#pragma unroll
                for (int i = 0; i < 8; i++) {
                    acc[2 * i]     = fma2(acc[2 * i],     cf2, v[i].x);
                    acc[2 * i + 1] = fma2(acc[2 * i + 1], cf2, v[i].y);
                }
            } else {
                const float w = __expf(d - m);
                l += w;
                const u64 w2 = pack2(w, w);
#pragma unroll
                for (int i = 0; i < 8; i++) {
                    acc[2 * i]     = fma2(v[i].x, w2, acc[2 * i]);
                    acc[2 * i + 1] = fma2(v[i].y, w2, acc[2 * i + 1]);
                }
            }
        }
        __syncthreads();   // all warps done with buffer bsel
        if (tid == 0 && st + NBUF < NSTAGES) {
            MBARRIER_EXPECT_TX(mbar0 + 8 * bsel, STAGE_BYTES);
            BULK_G2S(sbase + bsel * STAGE_BYTES,
                     src_base + (size_t)(st + NBUF) * STAGE_BYTES,
                     STAGE_BYTES, mbar0 + 8 * bsel);
        }
    }

    // ---- Combine 8 warp partials within the CTA, write split partials ----
    if (ln == 0) { msh[wid] = m; lsh[wid] = l; }
    __syncthreads();

    float M = msh[0];
#pragma unroll
    for (int w2i = 1; w2i < 8; w2i++) M = fmaxf(M, msh[w2i]);
    float L = 0.f;
#pragma unroll
    for (int w2i = 0; w2i < 8; w2i++) L += lsh[w2i] * __expf(msh[w2i] - M);
    const float f = __expf(m - M);

    // Reuse stage buffers as [8 warps][256 float4] combine scratch (32 KiB)
    // (no TMA in flight: issues stopped at st+NBUF >= NSTAGES)
    float4* comb = (float4*)smem;
#pragma unroll
    for (int i = 0; i < 8; i++) {
        float ax, ay, az, aw;
        unpack2(acc[2 * i],     ax, ay);
        unpack2(acc[2 * i + 1], az, aw);
        float4 t;
        t.x = ax * f; t.y = ay * f; t.z = az * f; t.w = aw * f;
        comb[wid * 256 + i * 32 + ln] = t;
    }
    __syncthreads();

    float4 s = comb[tid];
#pragma unroll
    for (int w2i = 1; w2i < 8; w2i++) {
        const float4 t = comb[w2i * 256 + tid];
        s.x += t.x; s.y += t.y; s.z += t.z; s.w += t.w;
    }
    ((float4*)g_num)[(size_t)(b * NSPLIT + sp) * 256 + tid] = s;
    if (tid == 0) {
        g_ml[(b * NSPLIT + sp) * 2 + 0] = M;
        g_ml[(b * NSPLIT + sp) * 2 + 1] = L;
        __threadfence();                      // release partials
        atomicAdd(&g_cnt[b], 1);              // signal combine CTA
    }
}

// ---------------- Launch ----------------
extern "C" void kernel_launch(void* const* d_in, const int* in_sizes, int n_in,
                              void* d_out, int out_size)
{
    const float* enc = (const float*)d_in[0];   // (64, 2048, 1024) f32
    const float* hn  = (const float*)d_in[1];   // (64, 1024) f32
    float* out = (float*)d_out;                 // (64, 1, 2048) f32

    cudaFuncSetAttribute(attn_kernel,
                         cudaFuncAttributeMaxDynamicSharedMemorySize, SMEM_TOTAL);

    attn_kernel<<<GRID, 256, SMEM_TOTAL>>>(enc, hn, out);
}

// round 16
// speedup vs baseline: 1.0011x; 1.0011x over previous
#include <cuda_runtime.h>
#include <cstdint>
#include <math_constants.h>

// ============================================================================
// AttentionEval (B=64, S=2048, H=1024 fp32): out = concat(h_n, softmax(h·EncT)·Enc)
//
// FINAL KERNEL — verified 3x at 84.7/84.8/84.8 us (R6/R14/R15).
// Design: split-KV online-softmax, single pass over enc_output (512 MiB).
//   - 512 work CTAs (64 batches x 8 splits), 256 threads, 2 CTAs/SM.
//   - Each work CTA streams its 1 MiB slice through a 3-deep cp.async.bulk
//     pipeline of 32 KiB (8-row) stages; warp w consumes row w per stage.
//   - Inner loop: packed fma.rn.f32x2 dot + warp-uniform rare-rescale branch.
//   - 64 combine CTAs (last wave) merge the 8 split partials per batch from
//     L2 and write the output, overlapped with the streaming waves.
// Bound: sm_103a LTS throughput ceiling (~6300 B/cyc, path-independent;
// measured 6.4-6.6 TB/s). Kernel time is within ~1 us of the 512 MiB floor;
// all 14 attempted structural deviations measured equal or worse.
// ============================================================================

#define BATCH      64
#define SEQ        2048
#define H_DIM      1024
#define NSPLIT     8
#define ROWS_PER_CTA (SEQ / NSPLIT)            // 256
#define STAGE_ROWS 8
#define NSTAGES    (ROWS_PER_CTA / STAGE_ROWS) // 32
#define NBUF       3
#define STAGE_BYTES (STAGE_ROWS * H_DIM * 4)   // 32768
#define SMEM_BUF_BYTES (NBUF * STAGE_BYTES)    // 98304
#define SMEM_TOTAL (SMEM_BUF_BYTES + 128)      // 98432 -> 2 CTAs/SM
#define WORK_CTAS  (BATCH * NSPLIT)            // 512
#define GRID       (WORK_CTAS + BATCH)         // 512 work + 64 combine

typedef unsigned long long u64;

// Cross-CTA scratch (allocation-free: __device__ globals, zero-initialized)
__device__ float g_num[BATCH * NSPLIT * H_DIM];   // per-split exp-weighted numerator
__device__ float g_ml[BATCH * NSPLIT * 2];        // per-split (M, L)
__device__ int   g_cnt[BATCH];                    // arrival counters (combine CTA resets)

// ---------------- PTX helpers ----------------
__device__ __forceinline__ uint32_t smem_u32(const void* p) {
    uint32_t a;
    asm("{ .reg .u64 t; cvta.to.shared.u64 t, %1; cvt.u32.u64 %0, t; }"
        : "=r"(a) : "l"(p));
    return a;
}

// Packed f32x2 ops (Blackwell FFMA2 — only reachable via PTX)
__device__ __forceinline__ u64 fma2(u64 a, u64 b, u64 c) {
    u64 d; asm("fma.rn.f32x2 %0, %1, %2, %3;" : "=l"(d) : "l"(a), "l"(b), "l"(c));
    return d;
}
__device__ __forceinline__ u64 add2(u64 a, u64 b) {
    u64 d; asm("add.rn.f32x2 %0, %1, %2;" : "=l"(d) : "l"(a), "l"(b));
    return d;
}
__device__ __forceinline__ u64 pack2(float lo, float hi) {
    u64 r; asm("mov.b64 %0, {%1, %2};" : "=l"(r) : "f"(lo), "f"(hi));
    return r;
}
__device__ __forceinline__ void unpack2(u64 v, float& lo, float& hi) {
    asm("mov.b64 {%0, %1}, %2;" : "=f"(lo), "=f"(hi) : "l"(v));
}

#define MBARRIER_INIT(addr, count) \
    asm volatile("mbarrier.init.shared.b64 [%0], %1;" \
                 :: "r"((uint32_t)(addr)), "r"((uint32_t)(count)) : "memory")

#define MBARRIER_EXPECT_TX(addr, bytes) \
    asm volatile("mbarrier.arrive.expect_tx.shared.b64 _, [%0], %1;" \
                 :: "r"((uint32_t)(addr)), "r"((uint32_t)(bytes)) : "memory")

#define MBARRIER_WAIT_PARITY(mbar_smem_addr, phase_parity) do { \
    uint32_t _mbar = (uint32_t)(mbar_smem_addr); \
    uint32_t _parity = (uint32_t)(phase_parity); \
    uint32_t _done; \
    asm volatile( \
        "{\n\t" \
        ".reg .pred p;\n\t" \
        "mbarrier.try_wait.parity.acquire.cta.shared::cta.b64 p, [%1], %2;\n\t" \
        "selp.b32 %0, 1, 0, p;\n\t" \
        "}" \
        : "=r"(_done) : "r"(_mbar), "r"(_parity) : "memory"); \
    if (!_done) { \
        asm volatile( \
            "{\n\t" \
            ".reg .pred P1;\n\t" \
            "WAIT_LOOP_%=:\n\t" \
            "mbarrier.try_wait.parity.acquire.cta.shared::cta.b64 P1, [%0], %1, 0x989680;\n\t" \
            "@P1 bra.uni WAIT_DONE_%=;\n\t" \
            "bra.uni WAIT_LOOP_%=;\n\t" \
            "WAIT_DONE_%=:\n\t" \
            "}" \
            :: "r"(_mbar), "r"(_parity) : "memory"); \
    } \
} while (0)

#define BULK_G2S(dst_smem, src_gmem, nbytes, mbar) \
    asm volatile("cp.async.bulk.shared::cluster.global.mbarrier::complete_tx::bytes " \
                 "[%0], [%1], %2, [%3];" \
                 :: "r"((uint32_t)(dst_smem)), "l"(src_gmem), \
                    "r"((uint32_t)(nbytes)), "r"((uint32_t)(mbar)) : "memory")

__global__ void __launch_bounds__(256, 2)
attn_kernel(const float* __restrict__ enc, const float* __restrict__ hn,
            float* __restrict__ out)
{
    const int tid = threadIdx.x;

    // ================= Combine role =================
    if (blockIdx.x >= WORK_CTAS) {
        const int b = blockIdx.x - WORK_CTAS;
        __shared__ int ready;
        if (tid == 0) {
            while (atomicAdd(&g_cnt[b], 0) != NSPLIT) __nanosleep(200);
            g_cnt[b] = 0;                 // self-reset for next graph replay
            ready = 1;
        }
        __syncthreads();
        (void)ready;
        __threadfence();                  // acquire partials

        float ml_m[NSPLIT], ml_l[NSPLIT];
#pragma unroll
        for (int s2 = 0; s2 < NSPLIT; s2++) {
            ml_m[s2] = g_ml[(b * NSPLIT + s2) * 2 + 0];
            ml_l[s2] = g_ml[(b * NSPLIT + s2) * 2 + 1];
        }
        float GM = ml_m[0];
#pragma unroll
        for (int s2 = 1; s2 < NSPLIT; s2++) GM = fmaxf(GM, ml_m[s2]);
        float GL = 0.f;
#pragma unroll
        for (int s2 = 0; s2 < NSPLIT; s2++) GL += ml_l[s2] * __expf(ml_m[s2] - GM);

        float4 a = make_float4(0.f, 0.f, 0.f, 0.f);
        const float4* num4 = (const float4*)g_num;
#pragma unroll
        for (int s2 = 0; s2 < NSPLIT; s2++) {
            const float fs = __expf(ml_m[s2] - GM);
            const float4 t = num4[(size_t)(b * NSPLIT + s2) * 256 + tid];
            a.x += fs * t.x; a.y += fs * t.y; a.z += fs * t.z; a.w += fs * t.w;
        }
        const float inv = 1.0f / GL;

        float4* out4 = (float4*)out;
        out4[(size_t)b * 512 + tid] = ((const float4*)(hn + (size_t)b * H_DIM))[tid];
        float4 ctx;
        ctx.x = a.x * inv; ctx.y = a.y * inv; ctx.z = a.z * inv; ctx.w = a.w * inv;
        out4[(size_t)b * 512 + 256 + tid] = ctx;
        return;
    }

    // ================= Work role =================
    extern __shared__ char smem[];
    const int wid = tid >> 5;
    const int ln  = tid & 31;
    const int b   = blockIdx.x / NSPLIT;
    const int sp  = blockIdx.x % NSPLIT;

    const char* src_base =
        (const char*)(enc + ((size_t)b * SEQ + (size_t)sp * ROWS_PER_CTA) * H_DIM);

    const uint32_t sbase = smem_u32(smem);
    const uint32_t mbar0 = sbase + SMEM_BUF_BYTES;
    float* msh = (float*)(smem + SMEM_BUF_BYTES + 32);
    float* lsh = msh + 8;

    if (tid == 0) {
#pragma unroll
        for (int s = 0; s < NBUF; s++) MBARRIER_INIT(mbar0 + 8 * s, 1);
    }
    __syncthreads();

    // h_n[b] as packed f32x2 pairs matching the per-lane column map
    const ulonglong2* h2 = (const ulonglong2*)(hn + (size_t)b * H_DIM);
    ulonglong2 hreg[8];
#pragma unroll
    for (int i = 0; i < 8; i++) hreg[i] = h2[i * 32 + ln];

    float m = -CUDART_INF_F;
    float l = 0.f;
    u64 acc[16];
#pragma unroll
    for (int i = 0; i < 16; i++) acc[i] = 0ull;

    // Prologue: fill the pipeline
    if (tid == 0) {
#pragma unroll
        for (int s = 0; s < NBUF; s++) {
            MBARRIER_EXPECT_TX(mbar0 + 8 * s, STAGE_BYTES);
            BULK_G2S(sbase + s * STAGE_BYTES,
                     src_base + (size_t)s * STAGE_BYTES,
                     STAGE_BYTES, mbar0 + 8 * s);
        }
    }

    for (int st = 0; st < NSTAGES; st++) {
        const int bsel = st % NBUF;
        const int par  = (st / NBUF) & 1;
        MBARRIER_WAIT_PARITY(mbar0 + 8 * bsel, par);

        // Warp wid consumes row wid of this 8-row stage
        {
            const ulonglong2* row = (const ulonglong2*)
                (smem + (size_t)bsel * STAGE_BYTES + (size_t)wid * (H_DIM * 4));
            ulonglong2 v[8];
#pragma unroll
            for (int i = 0; i < 8; i++) v[i] = row[i * 32 + ln];   // 16B lane stride: conflict-free

            // Packed dot: 16 fma2, 2 independent chains
            u64 p0 = 0ull, p1 = 0ull;
#pragma unroll
            for (int i = 0; i < 8; i++) {
                p0 = fma2(v[i].x, hreg[i].x, p0);
                p1 = fma2(v[i].y, hreg[i].y, p1);
            }
            float dl, dh;
            unpack2(add2(p0, p1), dl, dh);
            float d = dl + dh;
#pragma unroll
            for (int off = 16; off; off >>= 1)
                d += __shfl_xor_sync(0xffffffffu, d, off);

            // Warp-uniform branch: d identical across lanes
            if (d > m) {
                const float cf = __expf(m - d);    // exp(-inf)=0 on first row
                m = d;
                l = l * cf + 1.f;
                const u64 cf2 = pack2(cf, cf);
#pragma unroll
                for (int i = 0; i < 8; i++) {
                    acc[2 * i]     = fma2(acc[2 * i],     cf2, v[i].x);
                    acc[2 * i + 1] = fma2(acc[2 * i + 1], cf2, v[i].y);
                }
            } else {
                const float w = __expf(d - m);
                l += w;
                const u64 w2 = pack2(w, w);
#pragma unroll
                for (int i = 0; i < 8; i++) {
                    acc[2 * i]     = fma2(v[i].x, w2, acc[2 * i]);
                    acc[2 * i + 1] = fma2(v[i].y, w2, acc[2 * i + 1]);
                }
            }
        }
        __syncthreads();   // all warps done with buffer bsel
        if (tid == 0 && st + NBUF < NSTAGES) {
            MBARRIER_EXPECT_TX(mbar0 + 8 * bsel, STAGE_BYTES);
            BULK_G2S(sbase + bsel * STAGE_BYTES,
                     src_base + (size_t)(st + NBUF) * STAGE_BYTES,
                     STAGE_BYTES, mbar0 + 8 * bsel);
        }
    }

    // ---- Combine 8 warp partials within the CTA, write split partials ----
    if (ln == 0) { msh[wid] = m; lsh[wid] = l; }
    __syncthreads();

    float M = msh[0];
#pragma unroll
    for (int w2i = 1; w2i < 8; w2i++) M = fmaxf(M, msh[w2i]);
    float L = 0.f;
#pragma unroll
    for (int w2i = 0; w2i < 8; w2i++) L += lsh[w2i] * __expf(msh[w2i] - M);
    const float f = __expf(m - M);

    // Reuse stage buffers as [8 warps][256 float4] combine scratch (32 KiB)
    // (no TMA in flight: issues stopped at st+NBUF >= NSTAGES)
    float4* comb = (float4*)smem;
#pragma unroll
    for (int i = 0; i < 8; i++) {
        float ax, ay, az, aw;
        unpack2(acc[2 * i],     ax, ay);
        unpack2(acc[2 * i + 1], az, aw);
        float4 t;
        t.x = ax * f; t.y = ay * f; t.z = az * f; t.w = aw * f;
        comb[wid * 256 + i * 32 + ln] = t;
    }
    __syncthreads();

    float4 s = comb[tid];
#pragma unroll
    for (int w2i = 1; w2i < 8; w2i++) {
        const float4 t = comb[w2i * 256 + tid];
        s.x += t.x; s.y += t.y; s.z += t.z; s.w += t.w;
    }
    ((float4*)g_num)[(size_t)(b * NSPLIT + sp) * 256 + tid] = s;
    if (tid == 0) {
        g_ml[(b * NSPLIT + sp) * 2 + 0] = M;
        g_ml[(b * NSPLIT + sp) * 2 + 1] = L;
        __threadfence();                      // release partials
        atomicAdd(&g_cnt[b], 1);              // signal combine CTA
    }
}

// ---------------- Launch ----------------
extern "C" void kernel_launch(void* const* d_in, const int* in_sizes, int n_in,
                              void* d_out, int out_size)
{
    const float* enc = (const float*)d_in[0];   // (64, 2048, 1024) f32
    const float* hn  = (const float*)d_in[1];   // (64, 1024) f32
    float* out = (float*)d_out;                 // (64, 1, 2048) f32

    cudaFuncSetAttribute(attn_kernel,
                         cudaFuncAttributeMaxDynamicSharedMemorySize, SMEM_TOTAL);

    attn_kernel<<<GRID, 256, SMEM_TOTAL>>>(enc, hn, out);
}

// round 17
// speedup vs baseline: 1.0095x; 1.0084x over previous
#include <cuda_runtime.h>
#include <cstdint>
#include <math_constants.h>

// ============================================================================
// AttentionEval (B=64, S=2048, H=1024 fp32): out = concat(h_n, softmax(h·EncT)·Enc)
//
// FINAL KERNEL — verified 4x at 84.70/84.80/84.83/84.74 us (R6/R14/R15/R16).
// Design: split-KV online-softmax, single pass over enc_output (512 MiB).
//   - 512 work CTAs (64 batches x 8 splits), 256 threads, 2 CTAs/SM.
//   - Each work CTA streams its 1 MiB slice through a 3-deep cp.async.bulk
//     pipeline of 32 KiB (8-row) stages; warp w consumes row w per stage.
//   - Inner loop: packed fma.rn.f32x2 dot + warp-uniform rare-rescale branch.
//   - 64 combine CTAs (last wave) merge the 8 split partials per batch from
//     L2 and write the output, overlapped with the streaming waves.
// Bound: sm_103a LTS throughput ceiling (~6300 B/cyc, path-independent;
// measured 6.4-6.6 TB/s). Kernel time is within ~1-2 us of the 512 MiB floor;
// all 14 attempted structural deviations measured equal or worse.
// ============================================================================

#define BATCH      64
#define SEQ        2048
#define H_DIM      1024
#define NSPLIT     8
#define ROWS_PER_CTA (SEQ / NSPLIT)            // 256
#define STAGE_ROWS 8
#define NSTAGES    (ROWS_PER_CTA / STAGE_ROWS) // 32
#define NBUF       3
#define STAGE_BYTES (STAGE_ROWS * H_DIM * 4)   // 32768
#define SMEM_BUF_BYTES (NBUF * STAGE_BYTES)    // 98304
#define SMEM_TOTAL (SMEM_BUF_BYTES + 128)      // 98432 -> 2 CTAs/SM
#define WORK_CTAS  (BATCH * NSPLIT)            // 512
#define GRID       (WORK_CTAS + BATCH)         // 512 work + 64 combine

typedef unsigned long long u64;

// Cross-CTA scratch (allocation-free: __device__ globals, zero-initialized)
__device__ float g_num[BATCH * NSPLIT * H_DIM];   // per-split exp-weighted numerator
__device__ float g_ml[BATCH * NSPLIT * 2];        // per-split (M, L)
__device__ int   g_cnt[BATCH];                    // arrival counters (combine CTA resets)

// ---------------- PTX helpers ----------------
__device__ __forceinline__ uint32_t smem_u32(const void* p) {
    uint32_t a;
    asm("{ .reg .u64 t; cvta.to.shared.u64 t, %1; cvt.u32.u64 %0, t; }"
        : "=r"(a) : "l"(p));
    return a;
}

// Packed f32x2 ops (Blackwell FFMA2 — only reachable via PTX)
__device__ __forceinline__ u64 fma2(u64 a, u64 b, u64 c) {
    u64 d; asm("fma.rn.f32x2 %0, %1, %2, %3;" : "=l"(d) : "l"(a), "l"(b), "l"(c));
    return d;
}
__device__ __forceinline__ u64 add2(u64 a, u64 b) {
    u64 d; asm("add.rn.f32x2 %0, %1, %2;" : "=l"(d) : "l"(a), "l"(b));
    return d;
}
__device__ __forceinline__ u64 pack2(float lo, float hi) {
    u64 r; asm("mov.b64 %0, {%1, %2};" : "=l"(r) : "f"(lo), "f"(hi));
    return r;
}
__device__ __forceinline__ void unpack2(u64 v, float& lo, float& hi) {
    asm("mov.b64 {%0, %1}, %2;" : "=f"(lo), "=f"(hi) : "l"(v));
}

#define MBARRIER_INIT(addr, count) \
    asm volatile("mbarrier.init.shared.b64 [%0], %1;" \
                 :: "r"((uint32_t)(addr)), "r"((uint32_t)(count)) : "memory")

#define MBARRIER_EXPECT_TX(addr, bytes) \
    asm volatile("mbarrier.arrive.expect_tx.shared.b64 _, [%0], %1;" \
                 :: "r"((uint32_t)(addr)), "r"((uint32_t)(bytes)) : "memory")

#define MBARRIER_WAIT_PARITY(mbar_smem_addr, phase_parity) do { \
    uint32_t _mbar = (uint32_t)(mbar_smem_addr); \
    uint32_t _parity = (uint32_t)(phase_parity); \
    uint32_t _done; \
    asm volatile( \
        "{\n\t" \
        ".reg .pred p;\n\t" \
        "mbarrier.try_wait.parity.acquire.cta.shared::cta.b64 p, [%1], %2;\n\t" \
        "selp.b32 %0, 1, 0, p;\n\t" \
        "}" \
        : "=r"(_done) : "r"(_mbar), "r"(_parity) : "memory"); \
    if (!_done) { \
        asm volatile( \
            "{\n\t" \
            ".reg .pred P1;\n\t" \
            "WAIT_LOOP_%=:\n\t" \
            "mbarrier.try_wait.parity.acquire.cta.shared::cta.b64 P1, [%0], %1, 0x989680;\n\t" \
            "@P1 bra.uni WAIT_DONE_%=;\n\t" \
            "bra.uni WAIT_LOOP_%=;\n\t" \
            "WAIT_DONE_%=:\n\t" \
            "}" \
            :: "r"(_mbar), "r"(_parity) : "memory"); \
    } \
} while (0)

#define BULK_G2S(dst_smem, src_gmem, nbytes, mbar) \
    asm volatile("cp.async.bulk.shared::cluster.global.mbarrier::complete_tx::bytes " \
                 "[%0], [%1], %2, [%3];" \
                 :: "r"((uint32_t)(dst_smem)), "l"(src_gmem), \
                    "r"((uint32_t)(nbytes)), "r"((uint32_t)(mbar)) : "memory")

__global__ void __launch_bounds__(256, 2)
attn_kernel(const float* __restrict__ enc, const float* __restrict__ hn,
            float* __restrict__ out)
{
    const int tid = threadIdx.x;

    // ================= Combine role =================
    if (blockIdx.x >= WORK_CTAS) {
        const int b = blockIdx.x - WORK_CTAS;
        __shared__ int ready;
        if (tid == 0) {
            while (atomicAdd(&g_cnt[b], 0) != NSPLIT) __nanosleep(200);
            g_cnt[b] = 0;                 // self-reset for next graph replay
            ready = 1;
        }
        __syncthreads();
        (void)ready;
        __threadfence();                  // acquire partials

        float ml_m[NSPLIT], ml_l[NSPLIT];
#pragma unroll
        for (int s2 = 0; s2 < NSPLIT; s2++) {
            ml_m[s2] = g_ml[(b * NSPLIT + s2) * 2 + 0];
            ml_l[s2] = g_ml[(b * NSPLIT + s2) * 2 + 1];
        }
        float GM = ml_m[0];
#pragma unroll
        for (int s2 = 1; s2 < NSPLIT; s2++) GM = fmaxf(GM, ml_m[s2]);
        float GL = 0.f;
#pragma unroll
        for (int s2 = 0; s2 < NSPLIT; s2++) GL += ml_l[s2] * __expf(ml_m[s2] - GM);

        float4 a = make_float4(0.f, 0.f, 0.f, 0.f);
        const float4* num4 = (const float4*)g_num;
#pragma unroll
        for (int s2 = 0; s2 < NSPLIT; s2++) {
            const float fs = __expf(ml_m[s2] - GM);
            const float4 t = num4[(size_t)(b * NSPLIT + s2) * 256 + tid];
            a.x += fs * t.x; a.y += fs * t.y; a.z += fs * t.z; a.w += fs * t.w;
        }
        const float inv = 1.0f / GL;

        float4* out4 = (float4*)out;
        out4[(size_t)b * 512 + tid] = ((const float4*)(hn + (size_t)b * H_DIM))[tid];
        float4 ctx;
        ctx.x = a.x * inv; ctx.y = a.y * inv; ctx.z = a.z * inv; ctx.w = a.w * inv;
        out4[(size_t)b * 512 + 256 + tid] = ctx;
        return;
    }

    // ================= Work role =================
    extern __shared__ char smem[];
    const int wid = tid >> 5;
    const int ln  = tid & 31;
    const int b   = blockIdx.x / NSPLIT;
    const int sp  = blockIdx.x % NSPLIT;

    const char* src_base =
        (const char*)(enc + ((size_t)b * SEQ + (size_t)sp * ROWS_PER_CTA) * H_DIM);

    const uint32_t sbase = smem_u32(smem);
    const uint32_t mbar0 = sbase + SMEM_BUF_BYTES;
    float* msh = (float*)(smem + SMEM_BUF_BYTES + 32);
    float* lsh = msh + 8;

    if (tid == 0) {
#pragma unroll
        for (int s = 0; s < NBUF; s++) MBARRIER_INIT(mbar0 + 8 * s, 1);
    }
    __syncthreads();

    // h_n[b] as packed f32x2 pairs matching the per-lane column map
    const ulonglong2* h2 = (const ulonglong2*)(hn + (size_t)b * H_DIM);
    ulonglong2 hreg[8];
#pragma unroll
    for (int i = 0; i < 8; i++) hreg[i] = h2[i * 32 + ln];

    float m = -CUDART_INF_F;
    float l = 0.f;
    u64 acc[16];
#pragma unroll
    for (int i = 0; i < 16; i++) acc[i] = 0ull;

    // Prologue: fill the pipeline
    if (tid == 0) {
#pragma unroll
        for (int s = 0; s < NBUF; s++) {
            MBARRIER_EXPECT_TX(mbar0 + 8 * s, STAGE_BYTES);
            BULK_G2S(sbase + s * STAGE_BYTES,
                     src_base + (size_t)s * STAGE_BYTES,
                     STAGE_BYTES, mbar0 + 8 * s);
        }
    }

    for (int st = 0; st < NSTAGES; st++) {
        const int bsel = st % NBUF;
        const int par  = (st / NBUF) & 1;
        MBARRIER_WAIT_PARITY(mbar0 + 8 * bsel, par);

        // Warp wid consumes row wid of this 8-row stage
        {
            const ulonglong2* row = (const ulonglong2*)
                (smem + (size_t)bsel * STAGE_BYTES + (size_t)wid * (H_DIM * 4));
            ulonglong2 v[8];
#pragma unroll
            for (int i = 0; i < 8; i++) v[i] = row[i * 32 + ln];   // 16B lane stride: conflict-free

            // Packed dot: 16 fma2, 2 independent chains
            u64 p0 = 0ull, p1 = 0ull;
#pragma unroll
            for (int i = 0; i < 8; i++) {
                p0 = fma2(v[i].x, hreg[i].x, p0);
                p1 = fma2(v[i].y, hreg[i].y, p1);
            }
            float dl, dh;
            unpack2(add2(p0, p1), dl, dh);
            float d = dl + dh;
#pragma unroll
            for (int off = 16; off; off >>= 1)
                d += __shfl_xor_sync(0xffffffffu, d, off);

            // Warp-uniform branch: d identical across lanes
            if (d > m) {
                const float cf = __expf(m - d);    // exp(-inf)=0 on first row
                m = d;
                l = l * cf + 1.f;
                const u64 cf2 = pack2(cf, cf);
#pragma unroll
                for (int i = 0; i < 8; i++) {
                    acc[2 * i]     = fma2(acc[2 * i],     cf2, v[i].x);
                    acc[2 * i + 1] = fma2(acc[2 * i + 1], cf2, v[i].y);
                }
            } else {
                const float w = __expf(d - m);
                l += w;
                const u64 w2 = pack2(w, w);
#pragma unroll
                for (int i = 0; i < 8; i++) {
                    acc[2 * i]     = fma2(v[i].x, w2, acc[2 * i]);
                    acc[2 * i + 1] = fma2(v[i].y, w2, acc[2 * i + 1]);
                }
            }
        }
        __syncthreads();   // all warps done with buffer bsel
        if (tid == 0 && st + NBUF < NSTAGES) {
            MBARRIER_EXPECT_TX(mbar0 + 8 * bsel, STAGE_BYTES);
            BULK_G2S(sbase + bsel * STAGE_BYTES,
                     src_base + (size_t)(st + NBUF) * STAGE_BYTES,
                     STAGE_BYTES, mbar0 + 8 * bsel);
        }
    }

    // ---- Combine 8 warp partials within the CTA, write split partials ----
    if (ln == 0) { msh[wid] = m; lsh[wid] = l; }
    __syncthreads();

    float M = msh[0];
#pragma unroll
    for (int w2i = 1; w2i < 8; w2i++) M = fmaxf(M, msh[w2i]);
    float L = 0.f;
#pragma unroll
    for (int w2i = 0; w2i < 8; w2i++) L += lsh[w2i] * __expf(msh[w2i] - M);
    const float f = __expf(m - M);

    // Reuse stage buffers as [8 warps][256 float4] combine scratch (32 KiB)
    // (no TMA in flight: issues stopped at st+NBUF >= NSTAGES)
    float4* comb = (float4*)smem;
#pragma unroll
    for (int i = 0; i < 8; i++) {
        float ax, ay, az, aw;
        unpack2(acc[2 * i],     ax, ay);
        unpack2(acc[2 * i + 1], az, aw);
        float4 t;
        t.x = ax * f; t.y = ay * f; t.z = az * f; t.w = aw * f;
        comb[wid * 256 + i * 32 + ln] = t;
    }
    __syncthreads();

    float4 s = comb[tid];
#pragma unroll
    for (int w2i = 1; w2i < 8; w2i++) {
        const float4 t = comb[w2i * 256 + tid];
        s.x += t.x; s.y += t.y; s.z += t.z; s.w += t.w;
    }
    ((float4*)g_num)[(size_t)(b * NSPLIT + sp) * 256 + tid] = s;
    if (tid == 0) {
        g_ml[(b * NSPLIT + sp) * 2 + 0] = M;
        g_ml[(b * NSPLIT + sp) * 2 + 1] = L;
        __threadfence();                      // release partials
        atomicAdd(&g_cnt[b], 1);              // signal combine CTA
    }
}

// ---------------- Launch ----------------
extern "C" void kernel_launch(void* const* d_in, const int* in_sizes, int n_in,
                              void* d_out, int out_size)
{
    const float* enc = (const float*)d_in[0];   // (64, 2048, 1024) f32
    const float* hn  = (const float*)d_in[1];   // (64, 1024) f32
    float* out = (float*)d_out;                 // (64, 1, 2048) f32

    cudaFuncSetAttribute(attn_kernel,
                         cudaFuncAttributeMaxDynamicSharedMemorySize, SMEM_TOTAL);

    attn_kernel<<<GRID, 256, SMEM_TOTAL>>>(enc, hn, out);
}